// round 7
// baseline (speedup 1.0000x reference)
#include <cuda_runtime.h>
#include <cuda_fp16.h>
#include <cstdint>
#include <math.h>

// ---------------------------------------------------------------------------
// GRU cell, legacy mma path (tcgen05 rejected by harness PTX target sm_103).
// R7: 512-thread CTAs, 32x32 warp tiles -> 32 warps/SM (was 16) to cure the
// latency-bound 19.6%-issue profile. BK=64, NST=3, fp16 ldmatrix+mma.
// ---------------------------------------------------------------------------

#define BATCH   16384
#define HID     1024
#define KCAT    2048
#define BK      64            // k halves per stage (4 x k16 MMA steps)
#define NST     3
#define NTH     512

#define BM 128
#define BN 128
#define RS 72                               // smem row stride in halves (144 B)
#define A_STAGE_B (BM * RS * 2)             // 18432 B
#define B_STAGE_B (BN * RS * 2)             // 18432 B
#define STAGE_B   (A_STAGE_B + B_STAGE_B)   // 36864 B
#define SMEM_TOTAL (NST * STAGE_B)          // 110592 B

// -------------------------- device scratch ---------------------------------
__device__ __half g_A [BATCH * KCAT];
__device__ __half g_Wt[3][HID * KCAT];   // [n][k]
__device__ __half g_rh[BATCH * HID];
__device__ float  g_z [BATCH * HID];
__device__ float  g_hp[BATCH * HID];

// -------------------------- helpers ----------------------------------------
__device__ __forceinline__ void mma_f16(float* c, const uint32_t* a, const uint32_t* b) {
    asm volatile(
        "mma.sync.aligned.m16n8k16.row.col.f32.f16.f16.f32 "
        "{%0,%1,%2,%3}, {%4,%5,%6,%7}, {%8,%9}, {%0,%1,%2,%3};\n"
        : "+f"(c[0]), "+f"(c[1]), "+f"(c[2]), "+f"(c[3])
        : "r"(a[0]), "r"(a[1]), "r"(a[2]), "r"(a[3]),
          "r"(b[0]), "r"(b[1]));
}
__device__ __forceinline__ void ldsm4(uint32_t* r, uint32_t addr) {
    asm volatile("ldmatrix.sync.aligned.m8n8.x4.shared.b16 {%0,%1,%2,%3}, [%4];"
                 : "=r"(r[0]), "=r"(r[1]), "=r"(r[2]), "=r"(r[3]) : "r"(addr));
}
__device__ __forceinline__ void cp16(uint32_t smem_dst, const void* gsrc) {
    asm volatile("cp.async.cg.shared.global [%0], [%1], 16;" :: "r"(smem_dst), "l"(gsrc));
}
__device__ __forceinline__ void cp_commit() { asm volatile("cp.async.commit_group;"); }
template <int N>
__device__ __forceinline__ void cp_wait() { asm volatile("cp.async.wait_group %0;" :: "n"(N) : "memory"); }
__device__ __forceinline__ float sigmoidf_fast(float v) { return 1.0f / (1.0f + __expf(-v)); }

// ---------------------------------------------------------------------------
// Prep kernels
// ---------------------------------------------------------------------------
__global__ void prep_concat_kernel(const float* __restrict__ h,
                                   const float* __restrict__ x)
{
    size_t n8 = (size_t)BATCH * KCAT / 8;
    for (size_t i = (size_t)blockIdx.x * blockDim.x + threadIdx.x;
         i < n8; i += (size_t)gridDim.x * blockDim.x) {
        size_t e   = i * 8;
        size_t row = e >> 11;
        size_t col = e & (KCAT - 1);
        const float* src = (col < HID) ? (h + row * HID + col)
                                       : (x + row * HID + (col - HID));
        float4 v0 = ((const float4*)src)[0];
        float4 v1 = ((const float4*)src)[1];
        __half2 o[4];
        o[0] = __float22half2_rn(make_float2(v0.x, v0.y));
        o[1] = __float22half2_rn(make_float2(v0.z, v0.w));
        o[2] = __float22half2_rn(make_float2(v1.x, v1.y));
        o[3] = __float22half2_rn(make_float2(v1.z, v1.w));
        ((uint4*)g_A)[i] = *(uint4*)o;
    }
}

// transpose + convert: g_Wt[g][n][k] = half(W_g[k][n])
__global__ void prep_weights_kernel(const float* __restrict__ Wr,
                                    const float* __restrict__ Wz,
                                    const float* __restrict__ Wh)
{
    __shared__ float t[32][33];
    const float* src = (blockIdx.z == 0) ? Wr : (blockIdx.z == 1) ? Wz : Wh;
    __half* dst = g_Wt[blockIdx.z];
    int tx = threadIdx.x, ty = threadIdx.y;
    int c0 = blockIdx.x * 32;   // n
    int r0 = blockIdx.y * 32;   // k
    #pragma unroll
    for (int j = 0; j < 32; j += 8)
        t[ty + j][tx] = src[(size_t)(r0 + ty + j) * HID + c0 + tx];
    __syncthreads();
    #pragma unroll
    for (int j = 0; j < 32; j += 8)
        dst[(size_t)(c0 + ty + j) * KCAT + r0 + tx] = __float2half_rn(t[tx][ty + j]);
}

// ---------------------------------------------------------------------------
// Unified GEMM.  MODE 1: gates (A = g_A, stride KCAT).  MODE 2: h-tilde.
// 16 warps: warp_m = wid>>2 (0..3, 32-row band), warp_n = wid&3 (0..3, 32-col).
// ---------------------------------------------------------------------------
template <int MODE>
__global__ void __launch_bounds__(NTH, 2)
gru_gemm(const float* __restrict__ h, float* __restrict__ out)
{
    extern __shared__ char smem[];
    const uint32_t sbase = (uint32_t)__cvta_generic_to_shared(smem);
    const int tid    = threadIdx.x;
    const int lane   = tid & 31;
    const int wid    = tid >> 5;
    const int warp_m = wid >> 2;         // 0..3 -> 32-row band
    const int warp_n = wid & 3;          // 0..3 -> 32-col band

    int mat, kstart, KT, col0;
    const __half* Bmat;
    const __half* Amat;
    int astride;
    if (MODE == 1) {
        mat    = blockIdx.x >> 3;
        col0   = (blockIdx.x & 7) * BN;
        kstart = (mat == 2) ? HID : 0;
        KT     = (KCAT - kstart) / BK;   // 32 or 16
        Bmat   = g_Wt[mat];
        Amat   = g_A;  astride = KCAT;
    } else {
        mat    = 0;
        col0   = blockIdx.x * BN;
        kstart = 0;
        KT     = HID / BK;               // 16
        Bmat   = g_Wt[2];
        Amat   = g_rh; astride = HID;
    }
    const int row0 = blockIdx.y * BM;

    auto load_stage = [&](int kt) {
        const uint32_t so = sbase + (kt % NST) * STAGE_B;
        const int kbase = kstart + kt * BK;
        #pragma unroll
        for (int j = 0; j < 2; j++) {        // A: 128 rows x 8 16B-chunks
            int idx = tid + j * NTH;
            int r = idx >> 3, c = idx & 7;
            cp16(so + r * (RS * 2) + c * 16,
                 Amat + (size_t)(row0 + r) * astride + kbase + c * 8);
        }
        #pragma unroll
        for (int j = 0; j < 2; j++) {        // B: 128 n-rows x 8 chunks
            int idx = tid + j * NTH;
            int r = idx >> 3, c = idx & 7;
            cp16(so + A_STAGE_B + r * (RS * 2) + c * 16,
                 Bmat + (size_t)(col0 + r) * KCAT + kbase + c * 8);
        }
        cp_commit();
    };

    // per-thread ldmatrix base offsets (bytes within stage)
    uint32_t a_off[2];
    #pragma unroll
    for (int mt = 0; mt < 2; mt++)
        a_off[mt] = (warp_m * 32 + mt * 16 + (lane & 15)) * (RS * 2)
                  + ((lane >> 4) & 1) * 16;
    uint32_t b_off[2];
    #pragma unroll
    for (int nt2 = 0; nt2 < 2; nt2++)
        b_off[nt2] = A_STAGE_B
                   + (warp_n * 32 + nt2 * 16 + (lane & 7) + ((lane >> 4) & 1) * 8) * (RS * 2)
                   + ((lane >> 3) & 1) * 16;

    float acc[2][4][4];
    #pragma unroll
    for (int mt = 0; mt < 2; mt++)
        #pragma unroll
        for (int nt = 0; nt < 4; nt++)
            #pragma unroll
            for (int i = 0; i < 4; i++)
                acc[mt][nt][i] = 0.0f;

    load_stage(0);
    load_stage(1);

    for (int kt = 0; kt < KT; kt++) {
        if (kt < KT - 1) cp_wait<1>(); else cp_wait<0>();
        __syncthreads();                 // single barrier per iteration
        if (kt + 2 < KT) load_stage(kt + 2);

        const uint32_t so = sbase + (kt % NST) * STAGE_B;
        #pragma unroll
        for (int ks = 0; ks < 4; ks++) {     // four k16 steps per stage
            uint32_t a[2][4], b[2][4];
            #pragma unroll
            for (int mt = 0; mt < 2; mt++)
                ldsm4(a[mt], so + a_off[mt] + ks * 32);
            #pragma unroll
            for (int nt2 = 0; nt2 < 2; nt2++)
                ldsm4(b[nt2], so + b_off[nt2] + ks * 32);
            #pragma unroll
            for (int mt = 0; mt < 2; mt++)
                #pragma unroll
                for (int nt = 0; nt < 4; nt++)
                    mma_f16(acc[mt][nt], a[mt], &b[nt >> 1][(nt & 1) * 2]);
        }
        // no trailing barrier: 3-deep ring, next write to this stage is gated
        // by the next top-of-loop barrier.
    }

    // ---- epilogue ----
    #pragma unroll
    for (int mt = 0; mt < 2; mt++) {
        #pragma unroll
        for (int nt = 0; nt < 4; nt++) {
            int r = row0 + warp_m * 32 + mt * 16 + (lane >> 2);
            int c = col0 + warp_n * 32 + nt * 8 + (lane & 3) * 2;
            #pragma unroll
            for (int half_i = 0; half_i < 2; half_i++) {
                int rr = r + half_i * 8;
                size_t gi = (size_t)rr * HID + c;
                float v0 = acc[mt][nt][half_i * 2 + 0];
                float v1 = acc[mt][nt][half_i * 2 + 1];
                if (MODE == 1) {
                    if (mat == 0) {
                        float2 hv = *(const float2*)(h + gi);
                        __half2 o = __float22half2_rn(make_float2(
                            sigmoidf_fast(v0) * hv.x, sigmoidf_fast(v1) * hv.y));
                        *(__half2*)(g_rh + gi) = o;
                    } else if (mat == 1) {
                        float2 o = make_float2(sigmoidf_fast(v0), sigmoidf_fast(v1));
                        *(float2*)(g_z + gi) = o;
                    } else {
                        *(float2*)(g_hp + gi) = make_float2(v0, v1);
                    }
                } else {
                    float2 hp2 = *(const float2*)(g_hp + gi);
                    float2 z2  = *(const float2*)(g_z  + gi);
                    float2 hv2 = *(const float2*)(h    + gi);
                    float t0 = tanhf(v0 + hp2.x);
                    float t1 = tanhf(v1 + hp2.y);
                    float2 o;
                    o.x = hv2.x + z2.x * (t0 - hv2.x);
                    o.y = hv2.y + z2.y * (t1 - hv2.y);
                    *(float2*)(out + gi) = o;
                }
            }
        }
    }
}

// ---------------------------------------------------------------------------

extern "C" void kernel_launch(void* const* d_in, const int* in_sizes, int n_in,
                              void* d_out, int out_size)
{
    const float* h  = (const float*)d_in[0];
    const float* x  = (const float*)d_in[1];
    const float* Wr = (const float*)d_in[2];
    const float* Wz = (const float*)d_in[3];
    const float* Wh = (const float*)d_in[4];
    float* out = (float*)d_out;

    cudaFuncSetAttribute(gru_gemm<1>, cudaFuncAttributeMaxDynamicSharedMemorySize, SMEM_TOTAL);
    cudaFuncSetAttribute(gru_gemm<2>, cudaFuncAttributeMaxDynamicSharedMemorySize, SMEM_TOTAL);

    prep_concat_kernel <<<2048, 256>>>(h, x);
    dim3 gT(HID / 32, KCAT / 32, 3);
    prep_weights_kernel<<<gT, dim3(32, 8)>>>(Wr, Wz, Wh);

    // Phase 1: x-fastest raster -> the 24 column-CTAs of one row panel share A in L2.
    dim3 g1(24, BATCH / BM);
    gru_gemm<1><<<g1, NTH, SMEM_TOTAL>>>(h, out);

    dim3 g2(HID / BN, BATCH / BM);   // (8, 128)
    gru_gemm<2><<<g2, NTH, SMEM_TOTAL>>>(h, out);
}